// round 3
// baseline (speedup 1.0000x reference)
#include <cuda_runtime.h>
#include <cstddef>

// ---------------------------------------------------------------------------
// HyperNodeAggregation: out = bmm(V, softmax(Q Kᵀ)ᵀ) with 1x1-conv Q/K/V.
// Restructured: E_b = Wq (Wk G_b)ᵀ + u1 bkᵀ + bq u2ᵀ,  G_b = X_b X_bᵀ.
// All fp32. Stages: rowsum -> gemv(u1,u2) -> G (split-K) -> reduce -> K̂ -> V
//                   -> E (rank-2 epilogue) -> softmax -> out.
// ---------------------------------------------------------------------------

#define BM 128
#define BN 128
#define BKD 16
#define TM 8
#define TN 8
#define NTHREADS 256

// Scratch (device globals: allocation-free rule)
__device__ float g_s   [4 * 512];
__device__ float g_u1  [4 * 4096];
__device__ float g_u2  [4 * 4096];
__device__ float g_Gp  [4 * 8 * 512 * 512];   // split-K partials, 32 MB
__device__ float g_G   [4 * 512 * 512];       // 4 MB
__device__ float g_Khat[4 * 4096 * 512];      // 32 MB
__device__ float g_v   [4 * 512 * 4096];      // 32 MB
__device__ float g_E   [67108864];            // 4*4096*4096, 256 MB

// ---------------------------------------------------------------------------
// Tiled SGEMM: C = A * op(B), A row-major [M,K] (lda), op(B)=B [K,N] (ldb) if
// !BT, else Bᵀ with B row-major [N,K] (ldb). Batched over grid.z with strides;
// optional split-K decomposition (nsplit>1) writing per-split partials.
// MODE 0: none; MODE 1: +e0[m]; MODE 2: +e0[m]*e1[n] + e2[m]*e3[n].
// All dims assumed multiples of tile sizes (true here: 512/4096).
// ---------------------------------------------------------------------------
template<int MODE, bool BT>
__global__ __launch_bounds__(NTHREADS)
void sgemm_kernel(const float* __restrict__ A, const float* __restrict__ B,
                  float* __restrict__ C,
                  int M, int N, int K, int lda, int ldb, int ldc,
                  long long sA, long long sB, long long sC,
                  int nsplit, int spA, int spB, long long spC,
                  const float* __restrict__ e0, long long se0,
                  const float* __restrict__ e1, long long se1,
                  const float* __restrict__ e2, long long se2,
                  const float* __restrict__ e3, long long se3)
{
    __shared__ __align__(16) float As[BKD][BM];
    __shared__ __align__(16) float Bs[BKD][BN];

    const int z   = blockIdx.z;
    const int bat = z / nsplit;
    const int sp  = z - bat * nsplit;

    const float* Ab = A + (long long)bat * sA + (long long)sp * spA
                        + (size_t)blockIdx.y * BM * lda;
    const float* Bb = B + (long long)bat * sB + (long long)sp * spB
                        + (BT ? (size_t)blockIdx.x * BN * ldb
                              : (size_t)blockIdx.x * BN);
    float* Cb = C + (long long)bat * sC + (long long)sp * spC;

    const int tid = threadIdx.x;
    const int tx  = tid & 15;   // N dir
    const int ty  = tid >> 4;   // M dir

    float acc[TM][TN];
    #pragma unroll
    for (int i = 0; i < TM; i++)
        #pragma unroll
        for (int j = 0; j < TN; j++) acc[i][j] = 0.f;

    for (int k0 = 0; k0 < K; k0 += BKD) {
        // A tile: 128 rows x 16 cols -> transposed into As[k][m]
        #pragma unroll
        for (int i = 0; i < 2; i++) {
            int idx = tid + i * NTHREADS;     // 0..511
            int row = idx >> 2;               // 0..127
            int c4  = (idx & 3) << 2;         // 0,4,8,12
            const float4 va = *reinterpret_cast<const float4*>(
                Ab + (size_t)row * lda + (k0 + c4));
            As[c4 + 0][row] = va.x;
            As[c4 + 1][row] = va.y;
            As[c4 + 2][row] = va.z;
            As[c4 + 3][row] = va.w;
        }
        if (BT) {
            #pragma unroll
            for (int i = 0; i < 2; i++) {
                int idx = tid + i * NTHREADS;
                int row = idx >> 2;           // n within tile
                int c4  = (idx & 3) << 2;
                const float4 vb = *reinterpret_cast<const float4*>(
                    Bb + (size_t)row * ldb + (k0 + c4));
                Bs[c4 + 0][row] = vb.x;
                Bs[c4 + 1][row] = vb.y;
                Bs[c4 + 2][row] = vb.z;
                Bs[c4 + 3][row] = vb.w;
            }
        } else {
            #pragma unroll
            for (int i = 0; i < 2; i++) {
                int idx = tid + i * NTHREADS;
                int row = idx >> 5;           // 0..15 (k within tile)
                int c4  = (idx & 31) << 2;    // 0..124
                *reinterpret_cast<float4*>(&Bs[row][c4]) =
                    *reinterpret_cast<const float4*>(
                        Bb + (size_t)(k0 + row) * ldb + c4);
            }
        }
        __syncthreads();

        #pragma unroll
        for (int kk = 0; kk < BKD; kk++) {
            const float4 a0 = *reinterpret_cast<const float4*>(&As[kk][ty * TM]);
            const float4 a1 = *reinterpret_cast<const float4*>(&As[kk][ty * TM + 4]);
            const float4 b0 = *reinterpret_cast<const float4*>(&Bs[kk][tx * TN]);
            const float4 b1 = *reinterpret_cast<const float4*>(&Bs[kk][tx * TN + 4]);
            const float a[TM] = {a0.x, a0.y, a0.z, a0.w, a1.x, a1.y, a1.z, a1.w};
            const float b[TN] = {b0.x, b0.y, b0.z, b0.w, b1.x, b1.y, b1.z, b1.w};
            #pragma unroll
            for (int i = 0; i < TM; i++)
                #pragma unroll
                for (int j = 0; j < TN; j++)
                    acc[i][j] = fmaf(a[i], b[j], acc[i][j]);
        }
        __syncthreads();
    }

    const float* e0b = (MODE >= 1) ? (e0 + (long long)bat * se0) : nullptr;
    const float* e1b = (MODE == 2) ? (e1 + (long long)bat * se1) : nullptr;
    const float* e2b = (MODE == 2) ? (e2 + (long long)bat * se2) : nullptr;
    const float* e3b = (MODE == 2) ? (e3 + (long long)bat * se3) : nullptr;

    const int n0 = blockIdx.x * BN + tx * TN;
    #pragma unroll
    for (int i = 0; i < TM; i++) {
        const int m = blockIdx.y * BM + ty * TM + i;
        float c0 = 0.f, c1 = 0.f;
        if (MODE == 1) c0 = e0b[m];
        if (MODE == 2) { c0 = e0b[m]; c1 = e2b[m]; }
        float r[TN];
        #pragma unroll
        for (int j = 0; j < TN; j++) {
            r[j] = acc[i][j];
            if (MODE == 1) r[j] += c0;
            if (MODE == 2) r[j] += c0 * e1b[n0 + j] + c1 * e3b[n0 + j];
        }
        float4* dst = reinterpret_cast<float4*>(Cb + (size_t)m * ldc + n0);
        dst[0] = make_float4(r[0], r[1], r[2], r[3]);
        dst[1] = make_float4(r[4], r[5], r[6], r[7]);
    }
}

// ---------------------------------------------------------------------------
// s[bat][c] = sum_n X[bat,c,n]
// ---------------------------------------------------------------------------
__global__ __launch_bounds__(256)
void rowsum_kernel(const float* __restrict__ X, float* __restrict__ s)
{
    const int bat = blockIdx.y, row = blockIdx.x;
    const float* xr = X + ((size_t)bat * 512 + row) * 4096;
    float acc = 0.f;
    for (int i = threadIdx.x; i < 4096; i += 256) acc += xr[i];
    __shared__ float sh[8];
    #pragma unroll
    for (int o = 16; o; o >>= 1) acc += __shfl_xor_sync(0xffffffffu, acc, o);
    if ((threadIdx.x & 31) == 0) sh[threadIdx.x >> 5] = acc;
    __syncthreads();
    if (threadIdx.x < 32) {
        float t = (threadIdx.x < 8) ? sh[threadIdx.x] : 0.f;
        #pragma unroll
        for (int o = 4; o; o >>= 1) t += __shfl_xor_sync(0xffffffffu, t, o);
        if (threadIdx.x == 0) s[(size_t)bat * 512 + row] = t;
    }
}

// ---------------------------------------------------------------------------
// y[bat][m] = W[m,:] . s[bat,:]  (+ bscale * bias[m]).  One warp per row.
// ---------------------------------------------------------------------------
__global__ __launch_bounds__(256)
void gemv_kernel(const float* __restrict__ W, const float* __restrict__ s,
                 const float* __restrict__ bias, float bscale,
                 float* __restrict__ y, int Mrows, int Kc)
{
    const int bat  = blockIdx.y;
    const int warp = threadIdx.x >> 5, lane = threadIdx.x & 31;
    const int row  = blockIdx.x * 8 + warp;
    const float* sv = s + (size_t)bat * Kc;
    const float* w  = W + (size_t)row * Kc;
    float acc = 0.f;
    for (int c = lane; c < Kc; c += 32) acc += w[c] * sv[c];
    #pragma unroll
    for (int o = 16; o; o >>= 1) acc += __shfl_xor_sync(0xffffffffu, acc, o);
    if (lane == 0) {
        float b = bias ? bscale * bias[row] : 0.f;
        y[(size_t)bat * Mrows + row] = acc + b;
    }
}

// ---------------------------------------------------------------------------
// G[bat] = sum over 8 split-K partials
// ---------------------------------------------------------------------------
__global__ __launch_bounds__(256)
void greduce_kernel(const float* __restrict__ Gp, float* __restrict__ G)
{
    const int bat = blockIdx.y;
    const int i = blockIdx.x * 256 + threadIdx.x;     // < 262144
    const float* p = Gp + (size_t)bat * 8 * 262144 + i;
    float acc = 0.f;
    #pragma unroll
    for (int sp = 0; sp < 8; sp++) acc += p[(size_t)sp * 262144];
    G[(size_t)bat * 262144 + i] = acc;
}

// ---------------------------------------------------------------------------
// In-place row softmax: rows of length 4096. grid(4096, batch).
// ---------------------------------------------------------------------------
__global__ __launch_bounds__(256)
void softmax_kernel(float* __restrict__ E)
{
    float* row = E + ((size_t)blockIdx.y * 4096 + blockIdx.x) * 4096;
    const int tid = threadIdx.x;
    float vals[16];
    float m = -1e30f;
    #pragma unroll
    for (int i = 0; i < 16; i++) {
        vals[i] = row[tid + i * 256];
        m = fmaxf(m, vals[i]);
    }
    __shared__ float sh[8];
    #pragma unroll
    for (int o = 16; o; o >>= 1) m = fmaxf(m, __shfl_xor_sync(0xffffffffu, m, o));
    if ((tid & 31) == 0) sh[tid >> 5] = m;
    __syncthreads();
    if (tid < 32) {
        float t = (tid < 8) ? sh[tid] : -1e30f;
        #pragma unroll
        for (int o = 4; o; o >>= 1) t = fmaxf(t, __shfl_xor_sync(0xffffffffu, t, o));
        if (tid == 0) sh[0] = t;
    }
    __syncthreads();
    m = sh[0];
    __syncthreads();                      // sh reused below
    float s = 0.f;
    #pragma unroll
    for (int i = 0; i < 16; i++) {
        vals[i] = __expf(vals[i] - m);
        s += vals[i];
    }
    #pragma unroll
    for (int o = 16; o; o >>= 1) s += __shfl_xor_sync(0xffffffffu, s, o);
    if ((tid & 31) == 0) sh[tid >> 5] = s;
    __syncthreads();
    if (tid < 32) {
        float t = (tid < 8) ? sh[tid] : 0.f;
        #pragma unroll
        for (int o = 4; o; o >>= 1) t += __shfl_xor_sync(0xffffffffu, t, o);
        if (tid == 0) sh[0] = t;
    }
    __syncthreads();
    const float inv = 1.0f / sh[0];
    #pragma unroll
    for (int i = 0; i < 16; i++)
        row[tid + i * 256] = vals[i] * inv;
}

// ---------------------------------------------------------------------------
extern "C" void kernel_launch(void* const* d_in, const int* in_sizes, int n_in,
                              void* d_out, int out_size)
{
    const float* x  = (const float*)d_in[0];   // [4,512,64,64] -> [4,512,4096]
    const float* Wq = (const float*)d_in[1];   // [4096,512]
    const float* bq = (const float*)d_in[2];   // [4096]
    const float* Wk = (const float*)d_in[3];   // [4096,512]
    const float* bk = (const float*)d_in[4];   // [4096]
    const float* Wv = (const float*)d_in[5];   // [512,512]
    const float* bv = (const float*)d_in[6];   // [512]
    float* out = (float*)d_out;                // [4,512,4096]

    float *s, *u1, *u2, *Gp, *G, *Khat, *V, *E;
    cudaGetSymbolAddress((void**)&s,    g_s);
    cudaGetSymbolAddress((void**)&u1,   g_u1);
    cudaGetSymbolAddress((void**)&u2,   g_u2);
    cudaGetSymbolAddress((void**)&Gp,   g_Gp);
    cudaGetSymbolAddress((void**)&G,    g_G);
    cudaGetSymbolAddress((void**)&Khat, g_Khat);
    cudaGetSymbolAddress((void**)&V,    g_v);
    cudaGetSymbolAddress((void**)&E,    g_E);

    const long long sX  = 512LL * 4096;       // batch stride of X / V
    const long long sE  = 4096LL * 4096;      // batch stride of E
    const long long sKh = 4096LL * 512;       // batch stride of Khat

    dim3 blk(NTHREADS);

    // s[b] = X_b . 1
    rowsum_kernel<<<dim3(512, 4), 256>>>(x, s);
    // u1 = Wq s + 4096*bq ; u2 = Wk s
    gemv_kernel<<<dim3(512, 4), 256>>>(Wq, s, bq, 4096.0f, u1, 4096, 512);
    gemv_kernel<<<dim3(512, 4), 256>>>(Wk, s, nullptr, 0.0f, u2, 4096, 512);

    // G_b = X_b X_bᵀ  (split-K over n: 8 splits of 512)
    sgemm_kernel<0, true><<<dim3(4, 4, 32), blk>>>(
        x, x, Gp, 512, 512, 512, 4096, 4096, 512,
        sX, sX, 8LL * 262144, /*nsplit=*/8, 512, 512, 262144,
        nullptr, 0, nullptr, 0, nullptr, 0, nullptr, 0);
    greduce_kernel<<<dim3(1024, 4), 256>>>(Gp, G);

    // Khat_b = Wk G_b   [4096, 512]
    sgemm_kernel<0, false><<<dim3(4, 32, 4), blk>>>(
        Wk, G, Khat, 4096, 512, 512, 512, 512, 512,
        0, 262144, sKh, 1, 0, 0, 0,
        nullptr, 0, nullptr, 0, nullptr, 0, nullptr, 0);

    // V_b = Wv X_b + bv   [512, 4096]
    sgemm_kernel<1, false><<<dim3(32, 4, 4), blk>>>(
        Wv, x, V, 512, 4096, 512, 512, 4096, 4096,
        0, sX, sX, 1, 0, 0, 0,
        bv, 0, nullptr, 0, nullptr, 0, nullptr, 0);

    // E_b = Wq Khat_bᵀ + u1 bkᵀ + bq u2ᵀ   [4096, 4096]
    sgemm_kernel<2, true><<<dim3(32, 32, 4), blk>>>(
        Wq, Khat, E, 4096, 4096, 512, 512, 512, 4096,
        0, sKh, sE, 1, 0, 0, 0,
        u1, 4096, bk, 0, bq, 0, u2, 4096);

    // P_b = softmax rows of E_b (in place)
    softmax_kernel<<<dim3(4096, 4), 256>>>(E);

    // out_b = V_b P_bᵀ   [512, 4096]
    sgemm_kernel<0, true><<<dim3(32, 4, 4), blk>>>(
        V, E, out, 512, 4096, 4096, 4096, 4096, 4096,
        sX, sE, sX, 1, 0, 0, 0,
        nullptr, 0, nullptr, 0, nullptr, 0, nullptr, 0);
}

// round 5
// speedup vs baseline: 2.6398x; 2.6398x over previous
#include <cuda_runtime.h>
#include <cuda_bf16.h>
#include <cstdint>
#include <cstddef>

// ===========================================================================
// HyperNodeAggregation via mma.sync bf16 multi-product GEMMs (fp32 accum).
//   E_b = Wq (Wk G_b)^T + u1 bk^T + bq u2^T,  G_b = X X^T (symmetric)
//   P = softmax(E);  V = Wv X + bv 1^T;  out = V P^T
// fp32 operands split into 2 bf16 planes; 4-product (exact) for G/Khat,
// 3-product for E/V/out. Target: plain sm_100 (no tcgen05 available).
// ===========================================================================

using bf16 = __nv_bfloat16;

constexpr int NB = 4, CH = 512, ND = 4096;

// ---------------- scratch (device globals; allocation-free rule) -----------
__device__ __align__(128) bf16 g_x [2][(size_t)NB * CH * ND];
__device__ __align__(128) bf16 g_xt[2][(size_t)NB * ND * CH];
__device__ __align__(128) bf16 g_wq[2][(size_t)ND * CH];
__device__ __align__(128) bf16 g_wk[2][(size_t)ND * CH];
__device__ __align__(128) bf16 g_wv[2][(size_t)CH * CH];
__device__ __align__(128) bf16 g_gg[2][(size_t)NB * CH * CH];
__device__ __align__(128) bf16 g_kh[2][(size_t)NB * ND * CH];
__device__ __align__(128) bf16 g_vv[2][(size_t)NB * CH * ND];
__device__ __align__(128) bf16 g_pp[2][(size_t)NB * ND * ND];
__device__ __align__(128) float g_E [(size_t)NB * ND * ND];
__device__ __align__(128) float g_Gp[(size_t)16 * CH * CH];
__device__ float g_s[NB * CH], g_u1[NB * ND], g_u2[NB * ND];

// ---------------- asm helpers (all plain sm_80+/sm_100-safe) ---------------
__device__ __forceinline__ uint32_t smem_to_u32(const void* p) {
    uint32_t a;
    asm("{ .reg .u64 t; cvta.to.shared.u64 t, %1; cvt.u32.u64 %0, t; }"
        : "=r"(a) : "l"(p));
    return a;
}
#define CPA16(s, g) \
    asm volatile("cp.async.cg.shared.global [%0], [%1], 16;" :: "r"(s), "l"(g) : "memory")
#define CPA_COMMIT() asm volatile("cp.async.commit_group;" ::: "memory")
#define CPA_WAIT(n)  asm volatile("cp.async.wait_group %0;" :: "n"(n) : "memory")
#define LDSM4(r0, r1, r2, r3, addr) \
    asm volatile("ldmatrix.sync.aligned.m8n8.x4.shared.b16 {%0,%1,%2,%3}, [%4];" \
        : "=r"(r0), "=r"(r1), "=r"(r2), "=r"(r3) : "r"(addr))
#define MMA_BF16(d, a, bb0, bb1) \
    asm volatile("mma.sync.aligned.m16n8k16.row.col.f32.bf16.bf16.f32 " \
        "{%0,%1,%2,%3}, {%4,%5,%6,%7}, {%8,%9}, {%0,%1,%2,%3};" \
        : "+f"((d)[0]), "+f"((d)[1]), "+f"((d)[2]), "+f"((d)[3]) \
        : "r"((a)[0]), "r"((a)[1]), "r"((a)[2]), "r"((a)[3]), "r"(bb0), "r"(bb1))

// ===========================================================================
// tc_gemm: C[128x128/CTA] = sum_{p<NPROD} A_{PA[p]} . B_{PB[p]}^T   (NT GEMM)
// A planes: [M,K] row-major (lda), B planes: [N,K] row-major (ldb), K-contig.
// BK=64 (128B rows, swizzle chunk ^= row&7). 3-stage cp.async pipeline.
// Warp layout 4x2, warp tile 32x64, m16n8k16 bf16 mma, fp32 accum.
// OMODE: 0 = fp32 store; 2 = fp32 + e0[m]e1[n] + e2[m]e3[n];
//        4 = 2-plane bf16 split store (+ optional bias e0[m]).
// Split-K via nsplit: z -> (bat, sp), k offset sp*Ksub, C offset z*sC.
// ===========================================================================
#define STAGE_B 65536           // 4 tiles * 16384 B
#define TILE_B2 16384           // 128 rows * 128 B

template<int NPROD, int OMODE>
__global__ void __launch_bounds__(256, 1)
tc_gemm(const bf16* __restrict__ a0, const bf16* __restrict__ a1,
        const bf16* __restrict__ b0, const bf16* __restrict__ b1,
        int Ksub, int nsplit, int lda, int ldb, long long sA, long long sB,
        float* __restrict__ Cf, bf16* __restrict__ c0, bf16* __restrict__ c1,
        int ldc, long long sC,
        const float* __restrict__ e0, long long se0,
        const float* __restrict__ e1, const float* __restrict__ e2,
        const float* __restrict__ e3, long long se3)
{
    extern __shared__ __align__(1024) char smem[];
    const uint32_t sb = smem_to_u32(smem);
    const int tid = threadIdx.x, wid = tid >> 5, lane = tid & 31;
    const int bx = blockIdx.x, by = blockIdx.y, z = blockIdx.z;
    const int bat = z / nsplit, sp = z - bat * nsplit;

    // ---- cp.async geometry: thread -> (row rr, 16B-chunk qq), fixed swizzle
    const int rr = tid >> 3;                 // 0..31
    const int qq = tid & 7;                  // 0..7
    const uint32_t sw = (uint32_t)((qq ^ (rr & 7)) << 4);
    const long long koffB = (long long)sp * Ksub * 2;

    const char* gbase[4];
    long long rowstep[4];
    {
        const long long la2 = (long long)lda * 2, lb2 = (long long)ldb * 2;
        const char* A0 = (const char*)(a0 + (long long)bat * sA) + (long long)(by * 128) * la2;
        const char* A1 = (const char*)(a1 + (long long)bat * sA) + (long long)(by * 128) * la2;
        const char* B0 = (const char*)(b0 + (long long)bat * sB) + (long long)(bx * 128) * lb2;
        const char* B1 = (const char*)(b1 + (long long)bat * sB) + (long long)(bx * 128) * lb2;
        gbase[0] = A0 + rr * la2 + qq * 16 + koffB;
        gbase[1] = A1 + rr * la2 + qq * 16 + koffB;
        gbase[2] = B0 + rr * lb2 + qq * 16 + koffB;
        gbase[3] = B1 + rr * lb2 + qq * 16 + koffB;
        rowstep[0] = la2 * 32; rowstep[1] = la2 * 32;
        rowstep[2] = lb2 * 32; rowstep[3] = lb2 * 32;
    }

    auto load_stage = [&](int ck, int stg) {
        const uint32_t s0 = sb + stg * STAGE_B;
        #pragma unroll
        for (int j = 0; j < 16; j++) {
            const int t = j >> 2, jj = j & 3;
            const uint32_t sa = s0 + t * TILE_B2 + (uint32_t)((jj * 32 + rr) * 128) + sw;
            const char* ga = gbase[t] + jj * rowstep[t] + (long long)ck * 128;
            CPA16(sa, ga);
        }
        CPA_COMMIT();
    };

    // ---- mma geometry
    const int mwarp = (wid & 3) * 32, nwarp = (wid >> 2) * 64;
    const int g8 = lane >> 3, id8 = lane & 7;
    const int aRow = ((g8 & 1) << 3) + id8, aC = g8 >> 1;
    const int bRow = (((g8 >> 1) & 1) << 3) + id8, bC = g8 & 1;

    float acc[64];
    #pragma unroll
    for (int i = 0; i < 64; i++) acc[i] = 0.f;

    constexpr int PA[4] = {0, 0, 1, 1};
    constexpr int PB[4] = {0, 1, 0, 1};

    const int nch = Ksub >> 6;
    load_stage(0, 0);
    load_stage(1, 1);

    for (int i = 0; i < nch; i++) {
        if (i == nch - 1) { CPA_WAIT(0); } else { CPA_WAIT(1); }
        __syncthreads();
        const uint32_t s0 = sb + (i % 3) * STAGE_B;
        #pragma unroll
        for (int p = 0; p < NPROD; p++) {
            const uint32_t at = s0 + PA[p] * TILE_B2;
            const uint32_t bt = s0 + (2 + PB[p]) * TILE_B2;
            #pragma unroll
            for (int kk = 0; kk < 4; kk++) {
                uint32_t a[2][4];
                #pragma unroll
                for (int mt = 0; mt < 2; mt++) {
                    const uint32_t ad = at + (uint32_t)((mwarp + mt * 16 + aRow) * 128)
                                      + (uint32_t)((((kk * 2 + aC) ^ id8)) << 4);
                    LDSM4(a[mt][0], a[mt][1], a[mt][2], a[mt][3], ad);
                }
                uint32_t b[4][4];
                #pragma unroll
                for (int nt = 0; nt < 4; nt++) {
                    const uint32_t bd = bt + (uint32_t)((nwarp + nt * 16 + bRow) * 128)
                                      + (uint32_t)((((kk * 2 + bC) ^ id8)) << 4);
                    LDSM4(b[nt][0], b[nt][1], b[nt][2], b[nt][3], bd);
                }
                #pragma unroll
                for (int mt = 0; mt < 2; mt++)
                    #pragma unroll
                    for (int nt = 0; nt < 4; nt++) {
                        MMA_BF16(&acc[(mt * 8 + nt * 2) * 4],     a[mt], b[nt][0], b[nt][1]);
                        MMA_BF16(&acc[(mt * 8 + nt * 2 + 1) * 4], a[mt], b[nt][2], b[nt][3]);
                    }
            }
        }
        __syncthreads();
        if (i + 2 < nch) load_stage(i + 2, (i + 2) % 3);
        else             CPA_COMMIT();              // keep group count uniform
    }

    // ---- epilogue
    const int er = lane >> 2, ec = (lane & 3) * 2;
    const float* e0b = e0 ? (e0 + (long long)bat * se0) : nullptr;
    const float* e3b = e3 ? (e3 + (long long)bat * se3) : nullptr;
    float* Cz = Cf ? (Cf + (long long)z * sC) : nullptr;
    bf16* c0z = c0 ? (c0 + (long long)z * sC) : nullptr;
    bf16* c1z = c1 ? (c1 + (long long)z * sC) : nullptr;

    #pragma unroll
    for (int mt = 0; mt < 2; mt++) {
        #pragma unroll
        for (int h = 0; h < 2; h++) {
            const int m = by * 128 + mwarp + mt * 16 + er + h * 8;
            float rowadd0 = 0.f, rowadd1 = 0.f, bias = 0.f;
            if (OMODE == 2) { rowadd0 = e0b[m]; rowadd1 = e2[m]; }
            if (OMODE == 4 && e0) bias = e0b[m];
            #pragma unroll
            for (int nt8 = 0; nt8 < 8; nt8++) {
                const int n = bx * 128 + nwarp + nt8 * 8 + ec;
                float v0 = acc[(mt * 8 + nt8) * 4 + h * 2];
                float v1 = acc[(mt * 8 + nt8) * 4 + h * 2 + 1];
                if (OMODE == 2) {
                    v0 += rowadd0 * e1[n]     + rowadd1 * e3b[n];
                    v1 += rowadd0 * e1[n + 1] + rowadd1 * e3b[n + 1];
                }
                if (OMODE == 0 || OMODE == 2) {
                    *reinterpret_cast<float2*>(Cz + (size_t)m * ldc + n) =
                        make_float2(v0, v1);
                } else {
                    v0 += bias; v1 += bias;
                    bf16 h0a = __float2bfloat16(v0);
                    bf16 h0b = __float2bfloat16(v1);
                    float r0 = v0 - __bfloat162float(h0a);
                    float r1 = v1 - __bfloat162float(h0b);
                    __nv_bfloat162 lo; lo.x = h0a; lo.y = h0b;
                    __nv_bfloat162 hi; hi.x = __float2bfloat16(r0); hi.y = __float2bfloat16(r1);
                    *reinterpret_cast<__nv_bfloat162*>(c0z + (size_t)m * ldc + n) = lo;
                    *reinterpret_cast<__nv_bfloat162*>(c1z + (size_t)m * ldc + n) = hi;
                }
            }
        }
    }
}

// ---------------- small kernels --------------------------------------------
__global__ void split2_kernel(const float* __restrict__ src, bf16* __restrict__ p0,
                              bf16* __restrict__ p1, size_t n)
{
    size_t i = (size_t)blockIdx.x * 256 + threadIdx.x;
    if (i >= n) return;
    float f = src[i];
    bf16 a = __float2bfloat16(f);
    p0[i] = a;
    p1[i] = __float2bfloat16(f - __bfloat162float(a));
}

__global__ void transpose_split_kernel(const float* __restrict__ X,
                                       bf16* __restrict__ t0, bf16* __restrict__ t1)
{
    __shared__ float tile[32][33];
    const int n0 = blockIdx.x * 32, c0 = blockIdx.y * 32, b = blockIdx.z;
    const int tx = threadIdx.x, ty = threadIdx.y;   // 32 x 8
    const float* Xb = X + (size_t)b * CH * ND;
    #pragma unroll
    for (int k = 0; k < 32; k += 8)
        tile[ty + k][tx] = Xb[(size_t)(c0 + ty + k) * ND + n0 + tx];
    __syncthreads();
    bf16* d0 = t0 + (size_t)b * ND * CH;
    bf16* d1 = t1 + (size_t)b * ND * CH;
    #pragma unroll
    for (int k = 0; k < 32; k += 8) {
        float f = tile[tx][ty + k];
        bf16 a = __float2bfloat16(f);
        const size_t o = (size_t)(n0 + ty + k) * CH + c0 + tx;
        d0[o] = a;
        d1[o] = __float2bfloat16(f - __bfloat162float(a));
    }
}

__global__ void greduce_split_kernel(const float* __restrict__ Gp,
                                     bf16* __restrict__ g0, bf16* __restrict__ g1)
{
    const int bat = blockIdx.y;
    const int i = blockIdx.x * 256 + threadIdx.x;      // < 262144
    const float* p = Gp + ((size_t)bat * 4) * 262144 + i;
    float f = 0.f;
    #pragma unroll
    for (int s = 0; s < 4; s++) f += p[(size_t)s * 262144];
    const size_t o = (size_t)bat * 262144 + i;
    bf16 a = __float2bfloat16(f);
    g0[o] = a;
    g1[o] = __float2bfloat16(f - __bfloat162float(a));
}

__global__ __launch_bounds__(256)
void rowsum_kernel(const float* __restrict__ X, float* __restrict__ s)
{
    const int bat = blockIdx.y, row = blockIdx.x;
    const float* xr = X + ((size_t)bat * CH + row) * ND;
    float acc = 0.f;
    for (int i = threadIdx.x; i < ND; i += 256) acc += xr[i];
    __shared__ float sh[8];
    #pragma unroll
    for (int o = 16; o; o >>= 1) acc += __shfl_xor_sync(0xffffffffu, acc, o);
    if ((threadIdx.x & 31) == 0) sh[threadIdx.x >> 5] = acc;
    __syncthreads();
    if (threadIdx.x < 32) {
        float t = (threadIdx.x < 8) ? sh[threadIdx.x] : 0.f;
        #pragma unroll
        for (int o = 4; o; o >>= 1) t += __shfl_xor_sync(0xffffffffu, t, o);
        if (threadIdx.x == 0) s[(size_t)bat * CH + row] = t;
    }
}

__global__ __launch_bounds__(256)
void gemv_kernel(const float* __restrict__ W, const float* __restrict__ s,
                 const float* __restrict__ bias, float bscale,
                 float* __restrict__ y, int Mrows, int Kc)
{
    const int bat = blockIdx.y;
    const int warp = threadIdx.x >> 5, lane = threadIdx.x & 31;
    const int row = blockIdx.x * 8 + warp;
    const float* sv = s + (size_t)bat * Kc;
    const float* w = W + (size_t)row * Kc;
    float acc = 0.f;
    for (int c = lane; c < Kc; c += 32) acc += w[c] * sv[c];
    #pragma unroll
    for (int o = 16; o; o >>= 1) acc += __shfl_xor_sync(0xffffffffu, acc, o);
    if (lane == 0) {
        float b = bias ? bscale * bias[row] : 0.f;
        y[(size_t)bat * Mrows + row] = acc + b;
    }
}

__global__ __launch_bounds__(256)
void softmax_split_kernel(const float* __restrict__ E,
                          bf16* __restrict__ p0, bf16* __restrict__ p1)
{
    const size_t ro = ((size_t)blockIdx.y * ND + blockIdx.x) * ND;
    const float* row = E + ro;
    const int tid = threadIdx.x;
    float vals[16];
    float m = -1e30f;
    #pragma unroll
    for (int i = 0; i < 16; i++) {
        vals[i] = row[tid + i * 256];
        m = fmaxf(m, vals[i]);
    }
    __shared__ float sh[8];
    #pragma unroll
    for (int o = 16; o; o >>= 1) m = fmaxf(m, __shfl_xor_sync(0xffffffffu, m, o));
    if ((tid & 31) == 0) sh[tid >> 5] = m;
    __syncthreads();
    if (tid < 32) {
        float t = (tid < 8) ? sh[tid] : -1e30f;
        #pragma unroll
        for (int o = 4; o; o >>= 1) t = fmaxf(t, __shfl_xor_sync(0xffffffffu, t, o));
        if (tid == 0) sh[0] = t;
    }
    __syncthreads();
    m = sh[0];
    __syncthreads();
    float s = 0.f;
    #pragma unroll
    for (int i = 0; i < 16; i++) { vals[i] = __expf(vals[i] - m); s += vals[i]; }
    #pragma unroll
    for (int o = 16; o; o >>= 1) s += __shfl_xor_sync(0xffffffffu, s, o);
    if ((tid & 31) == 0) sh[tid >> 5] = s;
    __syncthreads();
    if (tid < 32) {
        float t = (tid < 8) ? sh[tid] : 0.f;
        #pragma unroll
        for (int o = 4; o; o >>= 1) t += __shfl_xor_sync(0xffffffffu, t, o);
        if (tid == 0) sh[0] = t;
    }
    __syncthreads();
    const float inv = 1.0f / sh[0];
    #pragma unroll
    for (int i = 0; i < 16; i++) {
        float p = vals[i] * inv;
        bf16 a = __float2bfloat16(p);
        const size_t o = ro + tid + i * 256;
        p0[o] = a;
        p1[o] = __float2bfloat16(p - __bfloat162float(a));
    }
}

// ---------------------------------------------------------------------------
extern "C" void kernel_launch(void* const* d_in, const int* in_sizes, int n_in,
                              void* d_out, int out_size)
{
    const float* x  = (const float*)d_in[0];
    const float* Wq = (const float*)d_in[1];
    const float* bq = (const float*)d_in[2];
    const float* Wk = (const float*)d_in[3];
    const float* bk = (const float*)d_in[4];
    const float* Wv = (const float*)d_in[5];
    const float* bv = (const float*)d_in[6];
    float* out = (float*)d_out;

    bf16 *x0, *xt0, *wq0, *wk0, *wv0, *gg0, *kh0, *vv0, *pp0;
    float *E, *Gp, *s, *u1, *u2;
    cudaGetSymbolAddress((void**)&x0,  g_x);
    cudaGetSymbolAddress((void**)&xt0, g_xt);
    cudaGetSymbolAddress((void**)&wq0, g_wq);
    cudaGetSymbolAddress((void**)&wk0, g_wk);
    cudaGetSymbolAddress((void**)&wv0, g_wv);
    cudaGetSymbolAddress((void**)&gg0, g_gg);
    cudaGetSymbolAddress((void**)&kh0, g_kh);
    cudaGetSymbolAddress((void**)&vv0, g_vv);
    cudaGetSymbolAddress((void**)&pp0, g_pp);
    cudaGetSymbolAddress((void**)&E,  g_E);
    cudaGetSymbolAddress((void**)&Gp, g_Gp);
    cudaGetSymbolAddress((void**)&s,  g_s);
    cudaGetSymbolAddress((void**)&u1, g_u1);
    cudaGetSymbolAddress((void**)&u2, g_u2);

    const size_t PX = (size_t)NB * CH * ND;
    const size_t PW = (size_t)ND * CH;
    const size_t PV = (size_t)CH * CH;
    const size_t PG = (size_t)NB * CH * CH;
    const size_t PK = (size_t)NB * ND * CH;
    const size_t PP = (size_t)NB * ND * ND;
    bf16 *x1 = x0 + PX, *xt1 = xt0 + PX;
    bf16 *wq1 = wq0 + PW, *wk1 = wk0 + PW, *wv1 = wv0 + PV;
    bf16 *gg1 = gg0 + PG, *kh1 = kh0 + PK, *vv1 = vv0 + PX, *pp1 = pp0 + PP;

    const int SMEM = 3 * STAGE_B;   // 196608 B
    cudaFuncSetAttribute(tc_gemm<4, 0>, cudaFuncAttributeMaxDynamicSharedMemorySize, SMEM);
    cudaFuncSetAttribute(tc_gemm<4, 4>, cudaFuncAttributeMaxDynamicSharedMemorySize, SMEM);
    cudaFuncSetAttribute(tc_gemm<3, 4>, cudaFuncAttributeMaxDynamicSharedMemorySize, SMEM);
    cudaFuncSetAttribute(tc_gemm<3, 2>, cudaFuncAttributeMaxDynamicSharedMemorySize, SMEM);
    cudaFuncSetAttribute(tc_gemm<3, 0>, cudaFuncAttributeMaxDynamicSharedMemorySize, SMEM);

    // plane splits
    split2_kernel<<<(unsigned)((PX + 255) / 256), 256>>>(x, x0, x1, PX);
    transpose_split_kernel<<<dim3(128, 16, NB), dim3(32, 8)>>>(x, xt0, xt1);
    split2_kernel<<<(unsigned)((PW + 255) / 256), 256>>>(Wq, wq0, wq1, PW);
    split2_kernel<<<(unsigned)((PW + 255) / 256), 256>>>(Wk, wk0, wk1, PW);
    split2_kernel<<<(unsigned)((PV + 255) / 256), 256>>>(Wv, wv0, wv1, PV);

    // fp32 rank-1 pieces
    rowsum_kernel<<<dim3(CH, NB), 256>>>(x, s);
    gemv_kernel<<<dim3(ND / 8, NB), 256>>>(Wq, s, bq, (float)ND, u1, ND, CH);
    gemv_kernel<<<dim3(ND / 8, NB), 256>>>(Wk, s, nullptr, 0.f, u2, ND, CH);

    const long long sX = (long long)CH * ND;
    const long long sG = (long long)CH * CH;
    const long long sK = (long long)ND * CH;
    const long long sE = (long long)ND * ND;

    // G_b = X X^T  (split-K 4, fp32 partials), then reduce + split
    tc_gemm<4, 0><<<dim3(4, 4, 16), 256, SMEM>>>(
        x0, x1, x0, x1, 1024, 4, ND, ND, sX, sX,
        Gp, nullptr, nullptr, CH, sG,
        nullptr, 0, nullptr, nullptr, nullptr, 0);
    greduce_split_kernel<<<dim3(1024, NB), 256>>>(Gp, gg0, gg1);

    // Khat_b = Wk G_b  (G symmetric -> NT), 4-product, split2 output
    tc_gemm<4, 4><<<dim3(4, 32, NB), 256, SMEM>>>(
        wk0, wk1, gg0, gg1, CH, 1, CH, CH, 0, sG,
        nullptr, kh0, kh1, CH, sK,
        nullptr, 0, nullptr, nullptr, nullptr, 0);

    // V_b = Wv X_b + bv (B = X^T planes), 3-product, split2 + bias
    tc_gemm<3, 4><<<dim3(32, 4, NB), 256, SMEM>>>(
        wv0, wv1, xt0, xt1, CH, 1, CH, CH, 0, sK,
        nullptr, vv0, vv1, ND, sX,
        bv, 0, nullptr, nullptr, nullptr, 0);

    // E_b = Wq Khat^T + u1 bk^T + bq u2^T, 3-product, fp32 + rank-2
    tc_gemm<3, 2><<<dim3(32, 32, NB), 256, SMEM>>>(
        wq0, wq1, kh0, kh1, CH, 1, CH, CH, 0, sK,
        E, nullptr, nullptr, ND, sE,
        u1, ND, bk, bq, u2, ND);

    // P = softmax(E) -> 2 bf16 planes
    softmax_split_kernel<<<dim3(ND, NB), 256>>>(E, pp0, pp1);

    // out_b = V_b P_b^T, 3-product, fp32
    tc_gemm<3, 0><<<dim3(32, 4, NB), 256, SMEM>>>(
        vv0, vv1, pp0, pp1, ND, 1, ND, ND, sX, sE,
        out, nullptr, nullptr, ND, sX,
        nullptr, 0, nullptr, nullptr, nullptr, 0);
}

// round 6
// speedup vs baseline: 2.8333x; 1.0733x over previous
#include <cuda_runtime.h>
#include <cuda_bf16.h>
#include <cstdint>
#include <cstddef>

// ===========================================================================
// HyperNodeAggregation via mma.sync bf16 3-product GEMMs (fp32 accum).
//   E_b = Wq (Wk G_b)^T + u1 bk^T + bq u2^T,  G_b = X X^T (symmetric)
//   P = softmax(E);  V = Wv X + bv 1^T;  out = V P^T
// fp32 operands split into 2 bf16 planes; 3 products (a0b0 + a1b0 + a0b1)
// everywhere (residual ~2^-18). Fragment-reuse ordering: 12 LDSM / k16.
// ===========================================================================

using bf16 = __nv_bfloat16;

constexpr int NB = 4, CH = 512, ND = 4096;

// ---------------- scratch (device globals; allocation-free rule) -----------
__device__ __align__(128) bf16 g_x [2][(size_t)NB * CH * ND];
__device__ __align__(128) bf16 g_xt[2][(size_t)NB * ND * CH];
__device__ __align__(128) bf16 g_wq[2][(size_t)ND * CH];
__device__ __align__(128) bf16 g_wk[2][(size_t)ND * CH];
__device__ __align__(128) bf16 g_wv[2][(size_t)CH * CH];
__device__ __align__(128) bf16 g_gg[2][(size_t)NB * CH * CH];
__device__ __align__(128) bf16 g_kh[2][(size_t)NB * ND * CH];
__device__ __align__(128) bf16 g_vv[2][(size_t)NB * CH * ND];
__device__ __align__(128) bf16 g_pp[2][(size_t)NB * ND * ND];
__device__ __align__(128) float g_E [(size_t)NB * ND * ND];
__device__ __align__(128) float g_Gp[(size_t)16 * CH * CH];
__device__ float g_s[NB * CH], g_u1[NB * ND], g_u2[NB * ND];

// ---------------- asm helpers ----------------------------------------------
__device__ __forceinline__ uint32_t smem_to_u32(const void* p) {
    uint32_t a;
    asm("{ .reg .u64 t; cvta.to.shared.u64 t, %1; cvt.u32.u64 %0, t; }"
        : "=r"(a) : "l"(p));
    return a;
}
#define CPA16(s, g) \
    asm volatile("cp.async.cg.shared.global [%0], [%1], 16;" :: "r"(s), "l"(g) : "memory")
#define CPA_COMMIT() asm volatile("cp.async.commit_group;" ::: "memory")
#define CPA_WAIT(n)  asm volatile("cp.async.wait_group %0;" :: "n"(n) : "memory")
#define LDSM4(r0, r1, r2, r3, addr) \
    asm volatile("ldmatrix.sync.aligned.m8n8.x4.shared.b16 {%0,%1,%2,%3}, [%4];" \
        : "=r"(r0), "=r"(r1), "=r"(r2), "=r"(r3) : "r"(addr))
#define MMA_BF16(d, a, bb0, bb1) \
    asm volatile("mma.sync.aligned.m16n8k16.row.col.f32.bf16.bf16.f32 " \
        "{%0,%1,%2,%3}, {%4,%5,%6,%7}, {%8,%9}, {%0,%1,%2,%3};" \
        : "+f"((d)[0]), "+f"((d)[1]), "+f"((d)[2]), "+f"((d)[3]) \
        : "r"((a)[0]), "r"((a)[1]), "r"((a)[2]), "r"((a)[3]), "r"(bb0), "r"(bb1))

// ===========================================================================
// tc_gemm: C[128x128/CTA] = a0.b0^T + a1.b0^T + a0.b1^T   (NT GEMM, K-contig)
// BK=64 (128B rows, swizzle chunk ^= row&7). 3-stage cp.async pipeline.
// Warp layout 4x2, warp tile 32x64, m16n8k16 bf16 mma, fp32 accum.
// Fragment reuse per k16: LDSM a0,a1,b0 -> mma a0b0, a1b0 -> LDSM b1 -> a0b1.
// OMODE: 0 = fp32 store; 2 = fp32 + e0[m]e1[n] + e2[m]e3[n];
//        4 = 2-plane bf16 split store (+ optional bias e0[m]).
// Split-K via nsplit: z -> (bat, sp), k offset sp*Ksub, C offset z*sC.
// ===========================================================================
#define STAGE_B 65536           // 4 tiles * 16384 B
#define TILE_B2 16384           // 128 rows * 128 B

template<int OMODE>
__global__ void __launch_bounds__(256, 1)
tc_gemm(const bf16* __restrict__ a0, const bf16* __restrict__ a1,
        const bf16* __restrict__ b0, const bf16* __restrict__ b1,
        int Ksub, int nsplit, int lda, int ldb, long long sA, long long sB,
        float* __restrict__ Cf, bf16* __restrict__ c0, bf16* __restrict__ c1,
        int ldc, long long sC,
        const float* __restrict__ e0, long long se0,
        const float* __restrict__ e1, const float* __restrict__ e2,
        const float* __restrict__ e3, long long se3)
{
    extern __shared__ __align__(1024) char smem[];
    const uint32_t sb = smem_to_u32(smem);
    const int tid = threadIdx.x, wid = tid >> 5, lane = tid & 31;
    const int bx = blockIdx.x, by = blockIdx.y, z = blockIdx.z;
    const int bat = z / nsplit, sp = z - bat * nsplit;

    // ---- cp.async geometry
    const int rr = tid >> 3;                 // 0..31
    const int qq = tid & 7;                  // 0..7
    const uint32_t sw = (uint32_t)((qq ^ (rr & 7)) << 4);
    const long long koffB = (long long)sp * Ksub * 2;

    const char* gbase[4];
    long long rowstep[4];
    {
        const long long la2 = (long long)lda * 2, lb2 = (long long)ldb * 2;
        const char* A0 = (const char*)(a0 + (long long)bat * sA) + (long long)(by * 128) * la2;
        const char* A1 = (const char*)(a1 + (long long)bat * sA) + (long long)(by * 128) * la2;
        const char* B0 = (const char*)(b0 + (long long)bat * sB) + (long long)(bx * 128) * lb2;
        const char* B1 = (const char*)(b1 + (long long)bat * sB) + (long long)(bx * 128) * lb2;
        gbase[0] = A0 + rr * la2 + qq * 16 + koffB;
        gbase[1] = A1 + rr * la2 + qq * 16 + koffB;
        gbase[2] = B0 + rr * lb2 + qq * 16 + koffB;
        gbase[3] = B1 + rr * lb2 + qq * 16 + koffB;
        rowstep[0] = la2 * 32; rowstep[1] = la2 * 32;
        rowstep[2] = lb2 * 32; rowstep[3] = lb2 * 32;
    }

    auto load_stage = [&](int ck, int stg) {
        const uint32_t s0 = sb + stg * STAGE_B;
        #pragma unroll
        for (int j = 0; j < 16; j++) {
            const int t = j >> 2, jj = j & 3;
            const uint32_t sa = s0 + t * TILE_B2 + (uint32_t)((jj * 32 + rr) * 128) + sw;
            const char* ga = gbase[t] + jj * rowstep[t] + (long long)ck * 128;
            CPA16(sa, ga);
        }
        CPA_COMMIT();
    };

    // ---- mma geometry
    const int mwarp = (wid & 3) * 32, nwarp = (wid >> 2) * 64;
    const int g8 = lane >> 3, id8 = lane & 7;
    const int aRow = ((g8 & 1) << 3) + id8, aC = g8 >> 1;
    const int bRow = (((g8 >> 1) & 1) << 3) + id8, bC = g8 & 1;

    float acc[64];
    #pragma unroll
    for (int i = 0; i < 64; i++) acc[i] = 0.f;

    const int nch = Ksub >> 6;
    load_stage(0, 0);
    load_stage(1, 1);

    for (int i = 0; i < nch; i++) {
        if (i == nch - 1) { CPA_WAIT(0); } else { CPA_WAIT(1); }
        __syncthreads();
        const uint32_t s0 = sb + (i % 3) * STAGE_B;
        const uint32_t at0 = s0,               at1 = s0 + TILE_B2;
        const uint32_t bt0 = s0 + 2 * TILE_B2, bt1 = s0 + 3 * TILE_B2;

        #pragma unroll
        for (int kk = 0; kk < 4; kk++) {
            const uint32_t aoff = (uint32_t)(((kk * 2 + aC) ^ id8) << 4);
            const uint32_t boff = (uint32_t)(((kk * 2 + bC) ^ id8) << 4);

            uint32_t a0f[2][4], a1f[2][4], bf[4][4];
            #pragma unroll
            for (int mt = 0; mt < 2; mt++) {
                const uint32_t mrow = (uint32_t)((mwarp + mt * 16 + aRow) * 128);
                LDSM4(a0f[mt][0], a0f[mt][1], a0f[mt][2], a0f[mt][3], at0 + mrow + aoff);
                LDSM4(a1f[mt][0], a1f[mt][1], a1f[mt][2], a1f[mt][3], at1 + mrow + aoff);
            }
            #pragma unroll
            for (int nt = 0; nt < 4; nt++) {
                const uint32_t nrow = (uint32_t)((nwarp + nt * 16 + bRow) * 128);
                LDSM4(bf[nt][0], bf[nt][1], bf[nt][2], bf[nt][3], bt0 + nrow + boff);
            }
            // products a0.b0 and a1.b0
            #pragma unroll
            for (int mt = 0; mt < 2; mt++)
                #pragma unroll
                for (int nt = 0; nt < 4; nt++) {
                    MMA_BF16(&acc[(mt * 8 + nt * 2) * 4],     a0f[mt], bf[nt][0], bf[nt][1]);
                    MMA_BF16(&acc[(mt * 8 + nt * 2 + 1) * 4], a0f[mt], bf[nt][2], bf[nt][3]);
                    MMA_BF16(&acc[(mt * 8 + nt * 2) * 4],     a1f[mt], bf[nt][0], bf[nt][1]);
                    MMA_BF16(&acc[(mt * 8 + nt * 2 + 1) * 4], a1f[mt], bf[nt][2], bf[nt][3]);
                }
            // overwrite B regs with plane 1, product a0.b1
            #pragma unroll
            for (int nt = 0; nt < 4; nt++) {
                const uint32_t nrow = (uint32_t)((nwarp + nt * 16 + bRow) * 128);
                LDSM4(bf[nt][0], bf[nt][1], bf[nt][2], bf[nt][3], bt1 + nrow + boff);
            }
            #pragma unroll
            for (int mt = 0; mt < 2; mt++)
                #pragma unroll
                for (int nt = 0; nt < 4; nt++) {
                    MMA_BF16(&acc[(mt * 8 + nt * 2) * 4],     a0f[mt], bf[nt][0], bf[nt][1]);
                    MMA_BF16(&acc[(mt * 8 + nt * 2 + 1) * 4], a0f[mt], bf[nt][2], bf[nt][3]);
                }
        }
        __syncthreads();
        if (i + 2 < nch) load_stage(i + 2, (i + 2) % 3);
        else             CPA_COMMIT();              // keep group count uniform
    }

    // ---- epilogue
    const int er = lane >> 2, ec = (lane & 3) * 2;
    const float* e0b = e0 ? (e0 + (long long)bat * se0) : nullptr;
    const float* e3b = e3 ? (e3 + (long long)bat * se3) : nullptr;
    float* Cz = Cf ? (Cf + (long long)z * sC) : nullptr;
    bf16* c0z = c0 ? (c0 + (long long)z * sC) : nullptr;
    bf16* c1z = c1 ? (c1 + (long long)z * sC) : nullptr;

    #pragma unroll
    for (int mt = 0; mt < 2; mt++) {
        #pragma unroll
        for (int h = 0; h < 2; h++) {
            const int m = by * 128 + mwarp + mt * 16 + er + h * 8;
            float rowadd0 = 0.f, rowadd1 = 0.f, bias = 0.f;
            if (OMODE == 2) { rowadd0 = e0b[m]; rowadd1 = e2[m]; }
            if (OMODE == 4 && e0) bias = e0b[m];
            #pragma unroll
            for (int nt8 = 0; nt8 < 8; nt8++) {
                const int n = bx * 128 + nwarp + nt8 * 8 + ec;
                float v0 = acc[(mt * 8 + nt8) * 4 + h * 2];
                float v1 = acc[(mt * 8 + nt8) * 4 + h * 2 + 1];
                if (OMODE == 2) {
                    v0 += rowadd0 * e1[n]     + rowadd1 * e3b[n];
                    v1 += rowadd0 * e1[n + 1] + rowadd1 * e3b[n + 1];
                }
                if (OMODE == 0 || OMODE == 2) {
                    *reinterpret_cast<float2*>(Cz + (size_t)m * ldc + n) =
                        make_float2(v0, v1);
                } else {
                    v0 += bias; v1 += bias;
                    bf16 h0a = __float2bfloat16(v0);
                    bf16 h0b = __float2bfloat16(v1);
                    float r0 = v0 - __bfloat162float(h0a);
                    float r1 = v1 - __bfloat162float(h0b);
                    __nv_bfloat162 lo; lo.x = h0a; lo.y = h0b;
                    __nv_bfloat162 hi; hi.x = __float2bfloat16(r0); hi.y = __float2bfloat16(r1);
                    *reinterpret_cast<__nv_bfloat162*>(c0z + (size_t)m * ldc + n) = lo;
                    *reinterpret_cast<__nv_bfloat162*>(c1z + (size_t)m * ldc + n) = hi;
                }
            }
        }
    }
}

// ---------------- small kernels --------------------------------------------
__global__ void split2_kernel(const float* __restrict__ src, bf16* __restrict__ p0,
                              bf16* __restrict__ p1, size_t n)
{
    size_t i = (size_t)blockIdx.x * 256 + threadIdx.x;
    if (i >= n) return;
    float f = src[i];
    bf16 a = __float2bfloat16(f);
    p0[i] = a;
    p1[i] = __float2bfloat16(f - __bfloat162float(a));
}

__global__ void transpose_split_kernel(const float* __restrict__ X,
                                       bf16* __restrict__ t0, bf16* __restrict__ t1)
{
    __shared__ float tile[32][33];
    const int n0 = blockIdx.x * 32, c0 = blockIdx.y * 32, b = blockIdx.z;
    const int tx = threadIdx.x, ty = threadIdx.y;   // 32 x 8
    const float* Xb = X + (size_t)b * CH * ND;
    #pragma unroll
    for (int k = 0; k < 32; k += 8)
        tile[ty + k][tx] = Xb[(size_t)(c0 + ty + k) * ND + n0 + tx];
    __syncthreads();
    bf16* d0 = t0 + (size_t)b * ND * CH;
    bf16* d1 = t1 + (size_t)b * ND * CH;
    #pragma unroll
    for (int k = 0; k < 32; k += 8) {
        float f = tile[tx][ty + k];
        bf16 a = __float2bfloat16(f);
        const size_t o = (size_t)(n0 + ty + k) * CH + c0 + tx;
        d0[o] = a;
        d1[o] = __float2bfloat16(f - __bfloat162float(a));
    }
}

__global__ void greduce_split_kernel(const float* __restrict__ Gp,
                                     bf16* __restrict__ g0, bf16* __restrict__ g1)
{
    const int bat = blockIdx.y;
    const int i = blockIdx.x * 256 + threadIdx.x;      // < 262144
    const float* p = Gp + ((size_t)bat * 4) * 262144 + i;
    float f = 0.f;
    #pragma unroll
    for (int s = 0; s < 4; s++) f += p[(size_t)s * 262144];
    const size_t o = (size_t)bat * 262144 + i;
    bf16 a = __float2bfloat16(f);
    g0[o] = a;
    g1[o] = __float2bfloat16(f - __bfloat162float(a));
}

__global__ __launch_bounds__(256)
void rowsum_kernel(const float* __restrict__ X, float* __restrict__ s)
{
    const int bat = blockIdx.y, row = blockIdx.x;
    const float* xr = X + ((size_t)bat * CH + row) * ND;
    float acc = 0.f;
    for (int i = threadIdx.x; i < ND; i += 256) acc += xr[i];
    __shared__ float sh[8];
    #pragma unroll
    for (int o = 16; o; o >>= 1) acc += __shfl_xor_sync(0xffffffffu, acc, o);
    if ((threadIdx.x & 31) == 0) sh[threadIdx.x >> 5] = acc;
    __syncthreads();
    if (threadIdx.x < 32) {
        float t = (threadIdx.x < 8) ? sh[threadIdx.x] : 0.f;
        #pragma unroll
        for (int o = 4; o; o >>= 1) t += __shfl_xor_sync(0xffffffffu, t, o);
        if (threadIdx.x == 0) s[(size_t)bat * CH + row] = t;
    }
}

__global__ __launch_bounds__(256)
void gemv_kernel(const float* __restrict__ W, const float* __restrict__ s,
                 const float* __restrict__ bias, float bscale,
                 float* __restrict__ y, int Mrows, int Kc)
{
    const int bat = blockIdx.y;
    const int warp = threadIdx.x >> 5, lane = threadIdx.x & 31;
    const int row = blockIdx.x * 8 + warp;
    const float* sv = s + (size_t)bat * Kc;
    const float* w = W + (size_t)row * Kc;
    float acc = 0.f;
    for (int c = lane; c < Kc; c += 32) acc += w[c] * sv[c];
    #pragma unroll
    for (int o = 16; o; o >>= 1) acc += __shfl_xor_sync(0xffffffffu, acc, o);
    if (lane == 0) {
        float b = bias ? bscale * bias[row] : 0.f;
        y[(size_t)bat * Mrows + row] = acc + b;
    }
}

__global__ __launch_bounds__(256)
void softmax_split_kernel(const float* __restrict__ E,
                          bf16* __restrict__ p0, bf16* __restrict__ p1)
{
    const size_t ro = ((size_t)blockIdx.y * ND + blockIdx.x) * ND;
    const float* row = E + ro;
    const int tid = threadIdx.x;
    float vals[16];
    float m = -1e30f;
    #pragma unroll
    for (int i = 0; i < 16; i++) {
        vals[i] = row[tid + i * 256];
        m = fmaxf(m, vals[i]);
    }
    __shared__ float sh[8];
    #pragma unroll
    for (int o = 16; o; o >>= 1) m = fmaxf(m, __shfl_xor_sync(0xffffffffu, m, o));
    if ((tid & 31) == 0) sh[tid >> 5] = m;
    __syncthreads();
    if (tid < 32) {
        float t = (tid < 8) ? sh[tid] : -1e30f;
        #pragma unroll
        for (int o = 4; o; o >>= 1) t = fmaxf(t, __shfl_xor_sync(0xffffffffu, t, o));
        if (tid == 0) sh[0] = t;
    }
    __syncthreads();
    m = sh[0];
    __syncthreads();
    float s = 0.f;
    #pragma unroll
    for (int i = 0; i < 16; i++) { vals[i] = __expf(vals[i] - m); s += vals[i]; }
    #pragma unroll
    for (int o = 16; o; o >>= 1) s += __shfl_xor_sync(0xffffffffu, s, o);
    if ((tid & 31) == 0) sh[tid >> 5] = s;
    __syncthreads();
    if (tid < 32) {
        float t = (tid < 8) ? sh[tid] : 0.f;
        #pragma unroll
        for (int o = 4; o; o >>= 1) t += __shfl_xor_sync(0xffffffffu, t, o);
        if (tid == 0) sh[0] = t;
    }
    __syncthreads();
    const float inv = 1.0f / sh[0];
    #pragma unroll
    for (int i = 0; i < 16; i++) {
        float p = vals[i] * inv;
        bf16 a = __float2bfloat16(p);
        const size_t o = ro + tid + i * 256;
        p0[o] = a;
        p1[o] = __float2bfloat16(p - __bfloat162float(a));
    }
}

// ---------------------------------------------------------------------------
extern "C" void kernel_launch(void* const* d_in, const int* in_sizes, int n_in,
                              void* d_out, int out_size)
{
    const float* x  = (const float*)d_in[0];
    const float* Wq = (const float*)d_in[1];
    const float* bq = (const float*)d_in[2];
    const float* Wk = (const float*)d_in[3];
    const float* bk = (const float*)d_in[4];
    const float* Wv = (const float*)d_in[5];
    const float* bv = (const float*)d_in[6];
    float* out = (float*)d_out;

    bf16 *x0, *xt0, *wq0, *wk0, *wv0, *gg0, *kh0, *vv0, *pp0;
    float *E, *Gp, *s, *u1, *u2;
    cudaGetSymbolAddress((void**)&x0,  g_x);
    cudaGetSymbolAddress((void**)&xt0, g_xt);
    cudaGetSymbolAddress((void**)&wq0, g_wq);
    cudaGetSymbolAddress((void**)&wk0, g_wk);
    cudaGetSymbolAddress((void**)&wv0, g_wv);
    cudaGetSymbolAddress((void**)&gg0, g_gg);
    cudaGetSymbolAddress((void**)&kh0, g_kh);
    cudaGetSymbolAddress((void**)&vv0, g_vv);
    cudaGetSymbolAddress((void**)&pp0, g_pp);
    cudaGetSymbolAddress((void**)&E,  g_E);
    cudaGetSymbolAddress((void**)&Gp, g_Gp);
    cudaGetSymbolAddress((void**)&s,  g_s);
    cudaGetSymbolAddress((void**)&u1, g_u1);
    cudaGetSymbolAddress((void**)&u2, g_u2);

    const size_t PX = (size_t)NB * CH * ND;
    const size_t PW = (size_t)ND * CH;
    const size_t PV = (size_t)CH * CH;
    const size_t PG = (size_t)NB * CH * CH;
    const size_t PK = (size_t)NB * ND * CH;
    const size_t PP = (size_t)NB * ND * ND;
    bf16 *x1 = x0 + PX, *xt1 = xt0 + PX;
    bf16 *wq1 = wq0 + PW, *wk1 = wk0 + PW, *wv1 = wv0 + PV;
    bf16 *gg1 = gg0 + PG, *kh1 = kh0 + PK, *vv1 = vv0 + PX, *pp1 = pp0 + PP;

    const int SMEM = 3 * STAGE_B;   // 196608 B
    cudaFuncSetAttribute(tc_gemm<0>, cudaFuncAttributeMaxDynamicSharedMemorySize, SMEM);
    cudaFuncSetAttribute(tc_gemm<2>, cudaFuncAttributeMaxDynamicSharedMemorySize, SMEM);
    cudaFuncSetAttribute(tc_gemm<4>, cudaFuncAttributeMaxDynamicSharedMemorySize, SMEM);

    // plane splits
    split2_kernel<<<(unsigned)((PX + 255) / 256), 256>>>(x, x0, x1, PX);
    transpose_split_kernel<<<dim3(128, 16, NB), dim3(32, 8)>>>(x, xt0, xt1);
    split2_kernel<<<(unsigned)((PW + 255) / 256), 256>>>(Wq, wq0, wq1, PW);
    split2_kernel<<<(unsigned)((PW + 255) / 256), 256>>>(Wk, wk0, wk1, PW);
    split2_kernel<<<(unsigned)((PV + 255) / 256), 256>>>(Wv, wv0, wv1, PV);

    // fp32 rank-1 pieces
    rowsum_kernel<<<dim3(CH, NB), 256>>>(x, s);
    gemv_kernel<<<dim3(ND / 8, NB), 256>>>(Wq, s, bq, (float)ND, u1, ND, CH);
    gemv_kernel<<<dim3(ND / 8, NB), 256>>>(Wk, s, nullptr, 0.f, u2, ND, CH);

    const long long sX = (long long)CH * ND;
    const long long sG = (long long)CH * CH;
    const long long sK = (long long)ND * CH;
    const long long sE = (long long)ND * ND;

    // G_b = X X^T  (split-K 4, fp32 partials), then reduce + split
    tc_gemm<0><<<dim3(4, 4, 16), 256, SMEM>>>(
        x0, x1, x0, x1, 1024, 4, ND, ND, sX, sX,
        Gp, nullptr, nullptr, CH, sG,
        nullptr, 0, nullptr, nullptr, nullptr, 0);
    greduce_split_kernel<<<dim3(1024, NB), 256>>>(Gp, gg0, gg1);

    // Khat_b = Wk G_b  (G symmetric -> NT), split2 output
    tc_gemm<4><<<dim3(4, 32, NB), 256, SMEM>>>(
        wk0, wk1, gg0, gg1, CH, 1, CH, CH, 0, sG,
        nullptr, kh0, kh1, CH, sK,
        nullptr, 0, nullptr, nullptr, nullptr, 0);

    // V_b = Wv X_b + bv (B = X^T planes), split2 + bias
    tc_gemm<4><<<dim3(32, 4, NB), 256, SMEM>>>(
        wv0, wv1, xt0, xt1, CH, 1, CH, CH, 0, sK,
        nullptr, vv0, vv1, ND, sX,
        bv, 0, nullptr, nullptr, nullptr, 0);

    // E_b = Wq Khat^T + u1 bk^T + bq u2^T, fp32 + rank-2
    tc_gemm<2><<<dim3(32, 32, NB), 256, SMEM>>>(
        wq0, wq1, kh0, kh1, CH, 1, CH, CH, 0, sK,
        E, nullptr, nullptr, ND, sE,
        u1, ND, bk, bq, u2, ND);

    // P = softmax(E) -> 2 bf16 planes
    softmax_split_kernel<<<dim3(ND, NB), 256>>>(E, pp0, pp1);

    // out_b = V_b P_b^T, fp32
    tc_gemm<0><<<dim3(32, 4, NB), 256, SMEM>>>(
        vv0, vv1, pp0, pp1, ND, 1, ND, ND, sX, sE,
        out, nullptr, nullptr, ND, sX,
        nullptr, 0, nullptr, nullptr, nullptr, 0);
}

// round 7
// speedup vs baseline: 3.0831x; 1.0881x over previous
#include <cuda_runtime.h>
#include <cuda_bf16.h>
#include <cstdint>
#include <cstddef>

// ===========================================================================
// HyperNodeAggregation via mma.sync bf16 3-product GEMMs (fp32 accum).
//   E_b = Wq (Wk G_b)^T + u1 bk^T + bq u2^T,  G_b = X X^T (symmetric)
//   P = softmax(E);  V = Wv X + bv 1^T;  out = V P^T
// fp32 operands split into 2 bf16 planes; 3 products (a0b0 + a1b0 + a0b1).
// R7: CTA tile 128(M) x 256(N), warp tile 64x64, 2-stage pipeline —
//     16 LDSM / 96 MMA per warp-k16 (was 12/24) to unbind smem bandwidth.
// ===========================================================================

using bf16 = __nv_bfloat16;

constexpr int NB = 4, CH = 512, ND = 4096;

// ---------------- scratch (device globals; allocation-free rule) -----------
__device__ __align__(128) bf16 g_x [2][(size_t)NB * CH * ND];
__device__ __align__(128) bf16 g_xt[2][(size_t)NB * ND * CH];
__device__ __align__(128) bf16 g_wq[2][(size_t)ND * CH];
__device__ __align__(128) bf16 g_wk[2][(size_t)ND * CH];
__device__ __align__(128) bf16 g_wv[2][(size_t)CH * CH];
__device__ __align__(128) bf16 g_gg[2][(size_t)NB * CH * CH];
__device__ __align__(128) bf16 g_kh[2][(size_t)NB * ND * CH];
__device__ __align__(128) bf16 g_vv[2][(size_t)NB * CH * ND];
__device__ __align__(128) bf16 g_pp[2][(size_t)NB * ND * ND];
__device__ __align__(128) float g_E [(size_t)NB * ND * ND];
__device__ __align__(128) float g_Gp[(size_t)16 * CH * CH];
__device__ float g_s[NB * CH], g_u1[NB * ND], g_u2[NB * ND];

// ---------------- asm helpers ----------------------------------------------
__device__ __forceinline__ uint32_t smem_to_u32(const void* p) {
    uint32_t a;
    asm("{ .reg .u64 t; cvta.to.shared.u64 t, %1; cvt.u32.u64 %0, t; }"
        : "=r"(a) : "l"(p));
    return a;
}
#define CPA16(s, g) \
    asm volatile("cp.async.cg.shared.global [%0], [%1], 16;" :: "r"(s), "l"(g) : "memory")
#define CPA_COMMIT() asm volatile("cp.async.commit_group;" ::: "memory")
#define CPA_WAIT(n)  asm volatile("cp.async.wait_group %0;" :: "n"(n) : "memory")
#define LDSM4(r0, r1, r2, r3, addr) \
    asm volatile("ldmatrix.sync.aligned.m8n8.x4.shared.b16 {%0,%1,%2,%3}, [%4];" \
        : "=r"(r0), "=r"(r1), "=r"(r2), "=r"(r3) : "r"(addr))
#define MMA_BF16(d, a, bb0, bb1) \
    asm volatile("mma.sync.aligned.m16n8k16.row.col.f32.bf16.bf16.f32 " \
        "{%0,%1,%2,%3}, {%4,%5,%6,%7}, {%8,%9}, {%0,%1,%2,%3};" \
        : "+f"((d)[0]), "+f"((d)[1]), "+f"((d)[2]), "+f"((d)[3]) \
        : "r"((a)[0]), "r"((a)[1]), "r"((a)[2]), "r"((a)[3]), "r"(bb0), "r"(bb1))

// ===========================================================================
// tc_gemm: C[128x256/CTA] = a0.b0^T + a1.b0^T + a0.b1^T   (NT GEMM, K-contig)
// BK=64 (128B rows, swizzle chunk ^= row&7). 2-stage cp.async pipeline.
// 8 warps as 2(M) x 4(N); warp tile 64x64; m16n8k16 bf16 mma, fp32 accum.
// Per warp-k16: LDSM a0,a1 (8) + b0 (4) -> 64 MMA -> LDSM b1 (4) -> 32 MMA.
// OMODE: 0 = fp32 store; 2 = fp32 + e0[m]e1[n] + e2[m]e3[n];
//        4 = 2-plane bf16 split store (+ optional bias e0[m]).
// Split-K via nsplit: z -> (bat, sp), k offset sp*Ksub, C offset z*sC.
// ===========================================================================
#define TILE_A  16384           // 128 rows * 128 B
#define TILE_BB 32768           // 256 rows * 128 B
#define STAGE_B 98304           // 2*TILE_A + 2*TILE_BB

template<int OMODE>
__global__ void __launch_bounds__(256, 1)
tc_gemm(const bf16* __restrict__ a0, const bf16* __restrict__ a1,
        const bf16* __restrict__ b0, const bf16* __restrict__ b1,
        int Ksub, int nsplit, int lda, int ldb, long long sA, long long sB,
        float* __restrict__ Cf, bf16* __restrict__ c0, bf16* __restrict__ c1,
        int ldc, long long sC,
        const float* __restrict__ e0, long long se0,
        const float* __restrict__ e1, const float* __restrict__ e2,
        const float* __restrict__ e3, long long se3)
{
    extern __shared__ __align__(1024) char smem[];
    const uint32_t sb = smem_to_u32(smem);
    const int tid = threadIdx.x, wid = tid >> 5, lane = tid & 31;
    const int bx = blockIdx.x, by = blockIdx.y, z = blockIdx.z;
    const int bat = z / nsplit, sp = z - bat * nsplit;

    // ---- cp.async geometry: thread -> (row rr, 16B-chunk qq), fixed swizzle
    const int rr = tid >> 3;                 // 0..31
    const int qq = tid & 7;                  // 0..7
    const uint32_t sw = (uint32_t)((qq ^ (rr & 7)) << 4);
    const long long koffB = (long long)sp * Ksub * 2;

    const char* gA[2];
    const char* gB[2];
    long long rstepA, rstepB;
    {
        const long long la2 = (long long)lda * 2, lb2 = (long long)ldb * 2;
        gA[0] = (const char*)(a0 + (long long)bat * sA)
              + (long long)(by * 128) * la2 + rr * la2 + qq * 16 + koffB;
        gA[1] = (const char*)(a1 + (long long)bat * sA)
              + (long long)(by * 128) * la2 + rr * la2 + qq * 16 + koffB;
        gB[0] = (const char*)(b0 + (long long)bat * sB)
              + (long long)(bx * 256) * lb2 + rr * lb2 + qq * 16 + koffB;
        gB[1] = (const char*)(b1 + (long long)bat * sB)
              + (long long)(bx * 256) * lb2 + rr * lb2 + qq * 16 + koffB;
        rstepA = la2 * 32;
        rstepB = lb2 * 32;
    }

    auto load_stage = [&](int ck, int stg) {
        const uint32_t s0 = sb + stg * STAGE_B;
        #pragma unroll
        for (int t = 0; t < 2; t++) {
            #pragma unroll
            for (int jj = 0; jj < 4; jj++) {       // A: 128 rows
                const uint32_t sa = s0 + t * TILE_A
                                  + (uint32_t)((jj * 32 + rr) * 128) + sw;
                CPA16(sa, gA[t] + jj * rstepA + (long long)ck * 128);
            }
        }
        #pragma unroll
        for (int t = 0; t < 2; t++) {
            #pragma unroll
            for (int jj = 0; jj < 8; jj++) {       // B: 256 rows
                const uint32_t sa = s0 + 2 * TILE_A + t * TILE_BB
                                  + (uint32_t)((jj * 32 + rr) * 128) + sw;
                CPA16(sa, gB[t] + jj * rstepB + (long long)ck * 128);
            }
        }
        CPA_COMMIT();
    };

    // ---- mma geometry: warps 2(M) x 4(N), warp tile 64x64
    const int mwarp = (wid & 1) * 64, nwarp = (wid >> 1) * 64;
    const int g8 = lane >> 3, id8 = lane & 7;
    const int aRow = ((g8 & 1) << 3) + id8, aC = g8 >> 1;
    const int bRow = (((g8 >> 1) & 1) << 3) + id8, bC = g8 & 1;

    float acc[128];                                  // 4 m16 x 8 n8 x 4
    #pragma unroll
    for (int i = 0; i < 128; i++) acc[i] = 0.f;

    const int nch = Ksub >> 6;
    load_stage(0, 0);

    for (int i = 0; i < nch; i++) {
        if (i + 1 < nch) { load_stage(i + 1, (i + 1) & 1); CPA_WAIT(1); }
        else             { CPA_WAIT(0); }
        __syncthreads();
        const uint32_t s0 = sb + (i & 1) * STAGE_B;
        const uint32_t at0 = s0,                at1 = s0 + TILE_A;
        const uint32_t bt0 = s0 + 2 * TILE_A,   bt1 = s0 + 2 * TILE_A + TILE_BB;

        #pragma unroll
        for (int kk = 0; kk < 4; kk++) {
            const uint32_t aoff = (uint32_t)(((kk * 2 + aC) ^ id8) << 4);
            const uint32_t boff = (uint32_t)(((kk * 2 + bC) ^ id8) << 4);

            uint32_t a0f[4][4], a1f[4][4], bf[4][4];
            #pragma unroll
            for (int mt = 0; mt < 4; mt++) {
                const uint32_t mrow = (uint32_t)((mwarp + mt * 16 + aRow) * 128);
                LDSM4(a0f[mt][0], a0f[mt][1], a0f[mt][2], a0f[mt][3], at0 + mrow + aoff);
                LDSM4(a1f[mt][0], a1f[mt][1], a1f[mt][2], a1f[mt][3], at1 + mrow + aoff);
            }
            #pragma unroll
            for (int nt = 0; nt < 4; nt++) {
                const uint32_t nrow = (uint32_t)((nwarp + nt * 16 + bRow) * 128);
                LDSM4(bf[nt][0], bf[nt][1], bf[nt][2], bf[nt][3], bt0 + nrow + boff);
            }
            // products a0.b0 and a1.b0
            #pragma unroll
            for (int mt = 0; mt < 4; mt++)
                #pragma unroll
                for (int nt = 0; nt < 4; nt++) {
                    MMA_BF16(&acc[(mt * 8 + nt * 2) * 4],     a0f[mt], bf[nt][0], bf[nt][1]);
                    MMA_BF16(&acc[(mt * 8 + nt * 2 + 1) * 4], a0f[mt], bf[nt][2], bf[nt][3]);
                    MMA_BF16(&acc[(mt * 8 + nt * 2) * 4],     a1f[mt], bf[nt][0], bf[nt][1]);
                    MMA_BF16(&acc[(mt * 8 + nt * 2 + 1) * 4], a1f[mt], bf[nt][2], bf[nt][3]);
                }
            // overwrite B regs with plane 1, product a0.b1
            #pragma unroll
            for (int nt = 0; nt < 4; nt++) {
                const uint32_t nrow = (uint32_t)((nwarp + nt * 16 + bRow) * 128);
                LDSM4(bf[nt][0], bf[nt][1], bf[nt][2], bf[nt][3], bt1 + nrow + boff);
            }
            #pragma unroll
            for (int mt = 0; mt < 4; mt++)
                #pragma unroll
                for (int nt = 0; nt < 4; nt++) {
                    MMA_BF16(&acc[(mt * 8 + nt * 2) * 4],     a0f[mt], bf[nt][0], bf[nt][1]);
                    MMA_BF16(&acc[(mt * 8 + nt * 2 + 1) * 4], a0f[mt], bf[nt][2], bf[nt][3]);
                }
        }
        __syncthreads();
    }

    // ---- epilogue
    const int er = lane >> 2, ec = (lane & 3) * 2;
    const float* e0b = e0 ? (e0 + (long long)bat * se0) : nullptr;
    const float* e3b = e3 ? (e3 + (long long)bat * se3) : nullptr;
    float* Cz = Cf ? (Cf + (long long)z * sC) : nullptr;
    bf16* c0z = c0 ? (c0 + (long long)z * sC) : nullptr;
    bf16* c1z = c1 ? (c1 + (long long)z * sC) : nullptr;

    #pragma unroll
    for (int mt = 0; mt < 4; mt++) {
        #pragma unroll
        for (int h = 0; h < 2; h++) {
            const int m = by * 128 + mwarp + mt * 16 + er + h * 8;
            float rowadd0 = 0.f, rowadd1 = 0.f, bias = 0.f;
            if (OMODE == 2) { rowadd0 = e0b[m]; rowadd1 = e2[m]; }
            if (OMODE == 4 && e0) bias = e0b[m];
            #pragma unroll
            for (int nt8 = 0; nt8 < 8; nt8++) {
                const int n = bx * 256 + nwarp + nt8 * 8 + ec;
                float v0 = acc[(mt * 8 + nt8) * 4 + h * 2];
                float v1 = acc[(mt * 8 + nt8) * 4 + h * 2 + 1];
                if (OMODE == 2) {
                    v0 += rowadd0 * e1[n]     + rowadd1 * e3b[n];
                    v1 += rowadd0 * e1[n + 1] + rowadd1 * e3b[n + 1];
                }
                if (OMODE == 0 || OMODE == 2) {
                    *reinterpret_cast<float2*>(Cz + (size_t)m * ldc + n) =
                        make_float2(v0, v1);
                } else {
                    v0 += bias; v1 += bias;
                    bf16 h0a = __float2bfloat16(v0);
                    bf16 h0b = __float2bfloat16(v1);
                    float r0 = v0 - __bfloat162float(h0a);
                    float r1 = v1 - __bfloat162float(h0b);
                    __nv_bfloat162 lo; lo.x = h0a; lo.y = h0b;
                    __nv_bfloat162 hi; hi.x = __float2bfloat16(r0); hi.y = __float2bfloat16(r1);
                    *reinterpret_cast<__nv_bfloat162*>(c0z + (size_t)m * ldc + n) = lo;
                    *reinterpret_cast<__nv_bfloat162*>(c1z + (size_t)m * ldc + n) = hi;
                }
            }
        }
    }
}

// ---------------- small kernels --------------------------------------------
__global__ void split2_kernel(const float* __restrict__ src, bf16* __restrict__ p0,
                              bf16* __restrict__ p1, size_t n)
{
    size_t i = (size_t)blockIdx.x * 256 + threadIdx.x;
    if (i >= n) return;
    float f = src[i];
    bf16 a = __float2bfloat16(f);
    p0[i] = a;
    p1[i] = __float2bfloat16(f - __bfloat162float(a));
}

__global__ void transpose_split_kernel(const float* __restrict__ X,
                                       bf16* __restrict__ t0, bf16* __restrict__ t1)
{
    __shared__ float tile[32][33];
    const int n0 = blockIdx.x * 32, c0 = blockIdx.y * 32, b = blockIdx.z;
    const int tx = threadIdx.x, ty = threadIdx.y;   // 32 x 8
    const float* Xb = X + (size_t)b * CH * ND;
    #pragma unroll
    for (int k = 0; k < 32; k += 8)
        tile[ty + k][tx] = Xb[(size_t)(c0 + ty + k) * ND + n0 + tx];
    __syncthreads();
    bf16* d0 = t0 + (size_t)b * ND * CH;
    bf16* d1 = t1 + (size_t)b * ND * CH;
    #pragma unroll
    for (int k = 0; k < 32; k += 8) {
        float f = tile[tx][ty + k];
        bf16 a = __float2bfloat16(f);
        const size_t o = (size_t)(n0 + ty + k) * CH + c0 + tx;
        d0[o] = a;
        d1[o] = __float2bfloat16(f - __bfloat162float(a));
    }
}

__global__ void greduce_split_kernel(const float* __restrict__ Gp,
                                     bf16* __restrict__ g0, bf16* __restrict__ g1)
{
    const int bat = blockIdx.y;
    const int i = blockIdx.x * 256 + threadIdx.x;      // < 262144
    const float* p = Gp + ((size_t)bat * 4) * 262144 + i;
    float f = 0.f;
    #pragma unroll
    for (int s = 0; s < 4; s++) f += p[(size_t)s * 262144];
    const size_t o = (size_t)bat * 262144 + i;
    bf16 a = __float2bfloat16(f);
    g0[o] = a;
    g1[o] = __float2bfloat16(f - __bfloat162float(a));
}

__global__ __launch_bounds__(256)
void rowsum_kernel(const float* __restrict__ X, float* __restrict__ s)
{
    const int bat = blockIdx.y, row = blockIdx.x;
    const float* xr = X + ((size_t)bat * CH + row) * ND;
    float acc = 0.f;
    for (int i = threadIdx.x; i < ND; i += 256) acc += xr[i];
    __shared__ float sh[8];
    #pragma unroll
    for (int o = 16; o; o >>= 1) acc += __shfl_xor_sync(0xffffffffu, acc, o);
    if ((threadIdx.x & 31) == 0) sh[threadIdx.x >> 5] = acc;
    __syncthreads();
    if (threadIdx.x < 32) {
        float t = (threadIdx.x < 8) ? sh[threadIdx.x] : 0.f;
        #pragma unroll
        for (int o = 4; o; o >>= 1) t += __shfl_xor_sync(0xffffffffu, t, o);
        if (threadIdx.x == 0) s[(size_t)bat * CH + row] = t;
    }
}

__global__ __launch_bounds__(256)
void gemv_kernel(const float* __restrict__ W, const float* __restrict__ s,
                 const float* __restrict__ bias, float bscale,
                 float* __restrict__ y, int Mrows, int Kc)
{
    const int bat = blockIdx.y;
    const int warp = threadIdx.x >> 5, lane = threadIdx.x & 31;
    const int row = blockIdx.x * 8 + warp;
    const float* sv = s + (size_t)bat * Kc;
    const float* w = W + (size_t)row * Kc;
    float acc = 0.f;
    for (int c = lane; c < Kc; c += 32) acc += w[c] * sv[c];
    #pragma unroll
    for (int o = 16; o; o >>= 1) acc += __shfl_xor_sync(0xffffffffu, acc, o);
    if (lane == 0) {
        float b = bias ? bscale * bias[row] : 0.f;
        y[(size_t)bat * Mrows + row] = acc + b;
    }
}

__global__ __launch_bounds__(256)
void softmax_split_kernel(const float* __restrict__ E,
                          bf16* __restrict__ p0, bf16* __restrict__ p1)
{
    const size_t ro = ((size_t)blockIdx.y * ND + blockIdx.x) * ND;
    const float* row = E + ro;
    const int tid = threadIdx.x;
    float vals[16];
    float m = -1e30f;
    #pragma unroll
    for (int i = 0; i < 16; i++) {
        vals[i] = row[tid + i * 256];
        m = fmaxf(m, vals[i]);
    }
    __shared__ float sh[8];
    #pragma unroll
    for (int o = 16; o; o >>= 1) m = fmaxf(m, __shfl_xor_sync(0xffffffffu, m, o));
    if ((tid & 31) == 0) sh[tid >> 5] = m;
    __syncthreads();
    if (tid < 32) {
        float t = (tid < 8) ? sh[tid] : -1e30f;
        #pragma unroll
        for (int o = 4; o; o >>= 1) t = fmaxf(t, __shfl_xor_sync(0xffffffffu, t, o));
        if (tid == 0) sh[0] = t;
    }
    __syncthreads();
    m = sh[0];
    __syncthreads();
    float s = 0.f;
    #pragma unroll
    for (int i = 0; i < 16; i++) { vals[i] = __expf(vals[i] - m); s += vals[i]; }
    #pragma unroll
    for (int o = 16; o; o >>= 1) s += __shfl_xor_sync(0xffffffffu, s, o);
    if ((tid & 31) == 0) sh[tid >> 5] = s;
    __syncthreads();
    if (tid < 32) {
        float t = (tid < 8) ? sh[tid] : 0.f;
        #pragma unroll
        for (int o = 4; o; o >>= 1) t += __shfl_xor_sync(0xffffffffu, t, o);
        if (tid == 0) sh[0] = t;
    }
    __syncthreads();
    const float inv = 1.0f / sh[0];
    #pragma unroll
    for (int i = 0; i < 16; i++) {
        float p = vals[i] * inv;
        bf16 a = __float2bfloat16(p);
        const size_t o = ro + tid + i * 256;
        p0[o] = a;
        p1[o] = __float2bfloat16(p - __bfloat162float(a));
    }
}

// ---------------------------------------------------------------------------
extern "C" void kernel_launch(void* const* d_in, const int* in_sizes, int n_in,
                              void* d_out, int out_size)
{
    const float* x  = (const float*)d_in[0];
    const float* Wq = (const float*)d_in[1];
    const float* bq = (const float*)d_in[2];
    const float* Wk = (const float*)d_in[3];
    const float* bk = (const float*)d_in[4];
    const float* Wv = (const float*)d_in[5];
    const float* bv = (const float*)d_in[6];
    float* out = (float*)d_out;

    bf16 *x0, *xt0, *wq0, *wk0, *wv0, *gg0, *kh0, *vv0, *pp0;
    float *E, *Gp, *s, *u1, *u2;
    cudaGetSymbolAddress((void**)&x0,  g_x);
    cudaGetSymbolAddress((void**)&xt0, g_xt);
    cudaGetSymbolAddress((void**)&wq0, g_wq);
    cudaGetSymbolAddress((void**)&wk0, g_wk);
    cudaGetSymbolAddress((void**)&wv0, g_wv);
    cudaGetSymbolAddress((void**)&gg0, g_gg);
    cudaGetSymbolAddress((void**)&kh0, g_kh);
    cudaGetSymbolAddress((void**)&vv0, g_vv);
    cudaGetSymbolAddress((void**)&pp0, g_pp);
    cudaGetSymbolAddress((void**)&E,  g_E);
    cudaGetSymbolAddress((void**)&Gp, g_Gp);
    cudaGetSymbolAddress((void**)&s,  g_s);
    cudaGetSymbolAddress((void**)&u1, g_u1);
    cudaGetSymbolAddress((void**)&u2, g_u2);

    const size_t PX = (size_t)NB * CH * ND;
    const size_t PW = (size_t)ND * CH;
    const size_t PV = (size_t)CH * CH;
    const size_t PG = (size_t)NB * CH * CH;
    const size_t PK = (size_t)NB * ND * CH;
    const size_t PP = (size_t)NB * ND * ND;
    bf16 *x1 = x0 + PX, *xt1 = xt0 + PX;
    bf16 *wq1 = wq0 + PW, *wk1 = wk0 + PW, *wv1 = wv0 + PV;
    bf16 *gg1 = gg0 + PG, *kh1 = kh0 + PK, *vv1 = vv0 + PX, *pp1 = pp0 + PP;

    const int SMEM = 2 * STAGE_B;   // 196608 B
    cudaFuncSetAttribute(tc_gemm<0>, cudaFuncAttributeMaxDynamicSharedMemorySize, SMEM);
    cudaFuncSetAttribute(tc_gemm<2>, cudaFuncAttributeMaxDynamicSharedMemorySize, SMEM);
    cudaFuncSetAttribute(tc_gemm<4>, cudaFuncAttributeMaxDynamicSharedMemorySize, SMEM);

    // plane splits
    split2_kernel<<<(unsigned)((PX + 255) / 256), 256>>>(x, x0, x1, PX);
    transpose_split_kernel<<<dim3(128, 16, NB), dim3(32, 8)>>>(x, xt0, xt1);
    split2_kernel<<<(unsigned)((PW + 255) / 256), 256>>>(Wq, wq0, wq1, PW);
    split2_kernel<<<(unsigned)((PW + 255) / 256), 256>>>(Wk, wk0, wk1, PW);
    split2_kernel<<<(unsigned)((PV + 255) / 256), 256>>>(Wv, wv0, wv1, PV);

    // fp32 rank-1 pieces
    rowsum_kernel<<<dim3(CH, NB), 256>>>(x, s);
    gemv_kernel<<<dim3(ND / 8, NB), 256>>>(Wq, s, bq, (float)ND, u1, ND, CH);
    gemv_kernel<<<dim3(ND / 8, NB), 256>>>(Wk, s, nullptr, 0.f, u2, ND, CH);

    const long long sX = (long long)CH * ND;
    const long long sG = (long long)CH * CH;
    const long long sK = (long long)ND * CH;
    const long long sE = (long long)ND * ND;

    // G_b = X X^T  (split-K 4, fp32 partials), then reduce + split
    tc_gemm<0><<<dim3(2, 4, 16), 256, SMEM>>>(
        x0, x1, x0, x1, 1024, 4, ND, ND, sX, sX,
        Gp, nullptr, nullptr, CH, sG,
        nullptr, 0, nullptr, nullptr, nullptr, 0);
    greduce_split_kernel<<<dim3(1024, NB), 256>>>(Gp, gg0, gg1);

    // Khat_b = Wk G_b  (G symmetric -> NT), split2 output
    tc_gemm<4><<<dim3(2, 32, NB), 256, SMEM>>>(
        wk0, wk1, gg0, gg1, CH, 1, CH, CH, 0, sG,
        nullptr, kh0, kh1, CH, sK,
        nullptr, 0, nullptr, nullptr, nullptr, 0);

    // V_b = Wv X_b + bv (B = X^T planes), split2 + bias
    tc_gemm<4><<<dim3(16, 4, NB), 256, SMEM>>>(
        wv0, wv1, xt0, xt1, CH, 1, CH, CH, 0, sK,
        nullptr, vv0, vv1, ND, sX,
        bv, 0, nullptr, nullptr, nullptr, 0);

    // E_b = Wq Khat^T + u1 bk^T + bq u2^T, fp32 + rank-2
    tc_gemm<2><<<dim3(16, 32, NB), 256, SMEM>>>(
        wq0, wq1, kh0, kh1, CH, 1, CH, CH, 0, sK,
        E, nullptr, nullptr, ND, sE,
        u1, ND, bk, bq, u2, ND);

    // P = softmax(E) -> 2 bf16 planes
    softmax_split_kernel<<<dim3(ND, NB), 256>>>(E, pp0, pp1);

    // out_b = V_b P_b^T, fp32
    tc_gemm<0><<<dim3(16, 4, NB), 256, SMEM>>>(
        vv0, vv1, pp0, pp1, ND, 1, ND, ND, sX, sE,
        out, nullptr, nullptr, ND, sX,
        nullptr, 0, nullptr, nullptr, nullptr, 0);
}